// round 1
// baseline (speedup 1.0000x reference)
#include <cuda_runtime.h>

#define HIDDEN 256
#define WPB    8          // warps (= points) per block

#define C11f 1.0989010989010990f   // 1/(1-0.3^2)
#define C12f 0.3296703296703297f   // 0.3/(1-0.09)
#define C33f 0.3846153846153846f   // 1/(2*1.3)

// One hidden layer for one point (one warp): reads h/ax/ay (length 256) from
// this warp's shared buffers, computes z = h@W + b, zx = ax@W, zy = ay@W,
// applies tanh + tangent rule, writes results back to the same shared buffers
// and also returns them in registers (8 per lane).
__device__ __forceinline__ void hidden_layer(
    const float* __restrict__ W, const float* __restrict__ b,
    float* sh_h, float* sh_ax, float* sh_ay,
    int j0,
    float h[8], float ax[8], float ay[8])
{
    float z[8], zx[8], zy[8];
#pragma unroll
    for (int t = 0; t < 8; t++) { z[t] = b[j0 + t]; zx[t] = 0.f; zy[t] = 0.f; }

#pragma unroll 2
    for (int k = 0; k < HIDDEN; k += 4) {
        float4 h4  = *(const float4*)(sh_h  + k);
        float4 ax4 = *(const float4*)(sh_ax + k);
        float4 ay4 = *(const float4*)(sh_ay + k);
        const float* hp  = (const float*)&h4;
        const float* axp = (const float*)&ax4;
        const float* ayp = (const float*)&ay4;
#pragma unroll
        for (int kk = 0; kk < 4; kk++) {
            const float4* wr = (const float4*)(W + (size_t)(k + kk) * HIDDEN + j0);
            float4 w0 = wr[0];
            float4 w1 = wr[1];
            float wv[8] = {w0.x, w0.y, w0.z, w0.w, w1.x, w1.y, w1.z, w1.w};
            float hk = hp[kk], axk = axp[kk], ayk = ayp[kk];
#pragma unroll
            for (int t = 0; t < 8; t++) {
                z[t]  = fmaf(hk,  wv[t], z[t]);
                zx[t] = fmaf(axk, wv[t], zx[t]);
                zy[t] = fmaf(ayk, wv[t], zy[t]);
            }
        }
    }

    // all lanes must be done READING the previous layer before we overwrite
    __syncwarp();

#pragma unroll
    for (int t = 0; t < 8; t++) {
        float hh = tanhf(z[t]);
        float g  = 1.f - hh * hh;
        h[t]  = hh;
        ax[t] = g * zx[t];
        ay[t] = g * zy[t];
    }
    *(float4*)(sh_h  + j0)     = make_float4(h[0],  h[1],  h[2],  h[3]);
    *(float4*)(sh_h  + j0 + 4) = make_float4(h[4],  h[5],  h[6],  h[7]);
    *(float4*)(sh_ax + j0)     = make_float4(ax[0], ax[1], ax[2], ax[3]);
    *(float4*)(sh_ax + j0 + 4) = make_float4(ax[4], ax[5], ax[6], ax[7]);
    *(float4*)(sh_ay + j0)     = make_float4(ay[0], ay[1], ay[2], ay[3]);
    *(float4*)(sh_ay + j0 + 4) = make_float4(ay[4], ay[5], ay[6], ay[7]);
    __syncwarp();
}

__global__ __launch_bounds__(WPB * 32)
void pinn_kernel(
    const float* __restrict__ X,
    const float* __restrict__ W1, const float* __restrict__ b1,
    const float* __restrict__ W2, const float* __restrict__ b2,
    const float* __restrict__ W3, const float* __restrict__ b3,
    const float* __restrict__ Wo, const float* __restrict__ bo,
    float* __restrict__ out, int npoints)
{
    __shared__ float sh[WPB][3][HIDDEN];

    const int warp = threadIdx.x >> 5;
    const int lane = threadIdx.x & 31;
    const int p    = blockIdx.x * WPB + warp;
    const int j0   = lane * 8;

    const float x = X[2 * p];
    const float y = X[2 * p + 1];

    float* sh_h  = &sh[warp][0][0];
    float* sh_ax = &sh[warp][1][0];
    float* sh_ay = &sh[warp][2][0];

    float h[8], ax[8], ay[8];

    // ---- layer 1: z1 = x*W1[0,:] + y*W1[1,:] + b1 ----
#pragma unroll
    for (int t = 0; t < 8; t += 4) {
        float4 w0 = *(const float4*)(W1 + j0 + t);            // W1[0][j..]
        float4 w1 = *(const float4*)(W1 + HIDDEN + j0 + t);   // W1[1][j..]
        float4 bb = *(const float4*)(b1 + j0 + t);
        float wx[4] = {w0.x, w0.y, w0.z, w0.w};
        float wy[4] = {w1.x, w1.y, w1.z, w1.w};
        float bv[4] = {bb.x, bb.y, bb.z, bb.w};
#pragma unroll
        for (int i = 0; i < 4; i++) {
            float zz = fmaf(x, wx[i], fmaf(y, wy[i], bv[i]));
            float hh = tanhf(zz);
            float g  = 1.f - hh * hh;
            h[t + i]  = hh;
            ax[t + i] = g * wx[i];   // tangent wrt x
            ay[t + i] = g * wy[i];   // tangent wrt y
        }
    }
    *(float4*)(sh_h  + j0)     = make_float4(h[0],  h[1],  h[2],  h[3]);
    *(float4*)(sh_h  + j0 + 4) = make_float4(h[4],  h[5],  h[6],  h[7]);
    *(float4*)(sh_ax + j0)     = make_float4(ax[0], ax[1], ax[2], ax[3]);
    *(float4*)(sh_ax + j0 + 4) = make_float4(ax[4], ax[5], ax[6], ax[7]);
    *(float4*)(sh_ay + j0)     = make_float4(ay[0], ay[1], ay[2], ay[3]);
    *(float4*)(sh_ay + j0 + 4) = make_float4(ay[4], ay[5], ay[6], ay[7]);
    __syncwarp();

    // ---- layers 2 and 3 ----
    hidden_layer(W2, b2, sh_h, sh_ax, sh_ay, j0, h, ax, ay);
    hidden_layer(W3, b3, sh_h, sh_ax, sh_ay, j0, h, ax, ay);

    // ---- output layer: 6 dot products of length 256, from registers ----
    float pu = 0.f, pv = 0.f, pux = 0.f, pvx = 0.f, puy = 0.f, pvy = 0.f;
#pragma unroll
    for (int t = 0; t < 8; t++) {
        int k = j0 + t;
        float wo0 = Wo[2 * k];
        float wo1 = Wo[2 * k + 1];
        pu  = fmaf(h[t],  wo0, pu);
        pv  = fmaf(h[t],  wo1, pv);
        pux = fmaf(ax[t], wo0, pux);
        pvx = fmaf(ax[t], wo1, pvx);
        puy = fmaf(ay[t], wo0, puy);
        pvy = fmaf(ay[t], wo1, pvy);
    }
#pragma unroll
    for (int off = 16; off > 0; off >>= 1) {
        pu  += __shfl_xor_sync(0xFFFFFFFFu, pu,  off);
        pv  += __shfl_xor_sync(0xFFFFFFFFu, pv,  off);
        pux += __shfl_xor_sync(0xFFFFFFFFu, pux, off);
        pvx += __shfl_xor_sync(0xFFFFFFFFu, pvx, off);
        puy += __shfl_xor_sync(0xFFFFFFFFu, puy, off);
        pvy += __shfl_xor_sync(0xFFFFFFFFu, pvy, off);
    }

    if (lane == 0) {
        float u = pu + bo[0];
        float v = pv + bo[1];
        float u_x = pux, v_x = pvx;    // tangent tx -> (u_x, v_x)
        float u_y = puy, v_y = pvy;    // tangent ty -> (u_y, v_y)
        float u_xy = u_y + v_x;
        float sx  = C11f * u_x + C12f * v_y;
        float sy  = C12f * u_x + C11f * v_y;
        float sxy = C33f * u_xy;
        float sed = 0.5f * (sx * u_x + sy * v_y + sxy * u_xy);
        out[p]               = u;
        out[npoints + p]     = v;
        out[2 * npoints + p] = sx;
        out[3 * npoints + p] = sy;
        out[4 * npoints + p] = sxy;
        out[5 * npoints + p] = sed;
    }
}

extern "C" void kernel_launch(void* const* d_in, const int* in_sizes, int n_in,
                              void* d_out, int out_size)
{
    const float* X  = (const float*)d_in[0];
    const float* W1 = (const float*)d_in[1];
    const float* b1 = (const float*)d_in[2];
    const float* W2 = (const float*)d_in[3];
    const float* b2 = (const float*)d_in[4];
    const float* W3 = (const float*)d_in[5];
    const float* b3 = (const float*)d_in[6];
    const float* Wo = (const float*)d_in[7];
    const float* bo = (const float*)d_in[8];
    float* out = (float*)d_out;

    const int npoints = in_sizes[0] / 2;      // 4*65536 = 262144
    const int nblocks = (npoints + WPB - 1) / WPB;

    pinn_kernel<<<nblocks, WPB * 32>>>(X, W1, b1, W2, b2, W3, b3, Wo, bo,
                                       out, npoints);
}

// round 2
// speedup vs baseline: 1.5549x; 1.5549x over previous
#include <cuda_runtime.h>

#define HIDDEN 256
#define WPB    4          // warps per block
#define PPW    4          // points per warp

#define C11f 1.0989010989010990f   // 1/(1-0.3^2)
#define C12f 0.3296703296703297f   // 0.3/(1-0.09)
#define C33f 0.3846153846153846f   // 1/(2*1.3)

// sh[warp][vec][point][k]  vec: 0=h 1=ax 2=ay
__global__ __launch_bounds__(WPB * 32, 2)
void pinn_kernel(
    const float* __restrict__ X,
    const float* __restrict__ W1, const float* __restrict__ b1,
    const float* __restrict__ W2, const float* __restrict__ b2,
    const float* __restrict__ W3, const float* __restrict__ b3,
    const float* __restrict__ Wo, const float* __restrict__ bo,
    float* __restrict__ out, int npoints)
{
    __shared__ float sh[WPB][3][PPW][HIDDEN];   // 48 KB

    const int warp  = threadIdx.x >> 5;
    const int lane  = threadIdx.x & 31;
    const int pbase = (blockIdx.x * WPB + warp) * PPW;
    const int j0    = lane * 8;

    float h[PPW][8], ax[PPW][8], ay[PPW][8];

    // ---------------- layer 1 ----------------
    float xs[PPW], ys[PPW];
#pragma unroll
    for (int p = 0; p < PPW; p++) {
        xs[p] = X[2 * (pbase + p)];
        ys[p] = X[2 * (pbase + p) + 1];
    }
#pragma unroll
    for (int t = 0; t < 8; t += 4) {
        float4 w0 = *(const float4*)(W1 + j0 + t);           // W1[0][j..]
        float4 w1 = *(const float4*)(W1 + HIDDEN + j0 + t);  // W1[1][j..]
        float4 bb = *(const float4*)(b1 + j0 + t);
        float wx[4] = {w0.x, w0.y, w0.z, w0.w};
        float wy[4] = {w1.x, w1.y, w1.z, w1.w};
        float bv[4] = {bb.x, bb.y, bb.z, bb.w};
#pragma unroll
        for (int i = 0; i < 4; i++) {
#pragma unroll
            for (int p = 0; p < PPW; p++) {
                float zz = fmaf(xs[p], wx[i], fmaf(ys[p], wy[i], bv[i]));
                float hh = tanhf(zz);
                float g  = 1.f - hh * hh;
                h[p][t + i]  = hh;
                ax[p][t + i] = g * wx[i];
                ay[p][t + i] = g * wy[i];
            }
        }
    }
#pragma unroll
    for (int p = 0; p < PPW; p++) {
        *(float4*)(&sh[warp][0][p][j0])     = make_float4(h[p][0], h[p][1], h[p][2], h[p][3]);
        *(float4*)(&sh[warp][0][p][j0 + 4]) = make_float4(h[p][4], h[p][5], h[p][6], h[p][7]);
        *(float4*)(&sh[warp][1][p][j0])     = make_float4(ax[p][0], ax[p][1], ax[p][2], ax[p][3]);
        *(float4*)(&sh[warp][1][p][j0 + 4]) = make_float4(ax[p][4], ax[p][5], ax[p][6], ax[p][7]);
        *(float4*)(&sh[warp][2][p][j0])     = make_float4(ay[p][0], ay[p][1], ay[p][2], ay[p][3]);
        *(float4*)(&sh[warp][2][p][j0 + 4]) = make_float4(ay[p][4], ay[p][5], ay[p][6], ay[p][7]);
    }
    __syncwarp();

    // ---------------- layers 2 & 3 ----------------
#pragma unroll 1
    for (int layer = 0; layer < 2; layer++) {
        const float* W = (layer == 0) ? W2 : W3;
        const float* b = (layer == 0) ? b2 : b3;

        // init accumulators (reuse h/ax/ay registers; old values live in SMEM)
#pragma unroll
        for (int t = 0; t < 8; t++) {
            float bb = b[j0 + t];
#pragma unroll
            for (int p = 0; p < PPW; p++) { h[p][t] = bb; ax[p][t] = 0.f; ay[p][t] = 0.f; }
        }

#pragma unroll 1
        for (int k4 = 0; k4 < HIDDEN; k4 += 4) {
            float4 hv[PPW], axv[PPW], ayv[PPW];
#pragma unroll
            for (int p = 0; p < PPW; p++) {
                hv[p]  = *(const float4*)(&sh[warp][0][p][k4]);
                axv[p] = *(const float4*)(&sh[warp][1][p][k4]);
                ayv[p] = *(const float4*)(&sh[warp][2][p][k4]);
            }
#pragma unroll
            for (int kk = 0; kk < 4; kk++) {
                const float4* wr = (const float4*)(W + (size_t)(k4 + kk) * HIDDEN + j0);
                float4 w0 = wr[0];
                float4 w1 = wr[1];
                float wv[8] = {w0.x, w0.y, w0.z, w0.w, w1.x, w1.y, w1.z, w1.w};
#pragma unroll
                for (int p = 0; p < PPW; p++) {
                    float hk  = ((const float*)&hv[p])[kk];
                    float axk = ((const float*)&axv[p])[kk];
                    float ayk = ((const float*)&ayv[p])[kk];
#pragma unroll
                    for (int t = 0; t < 8; t++) {
                        h[p][t]  = fmaf(hk,  wv[t], h[p][t]);
                        ax[p][t] = fmaf(axk, wv[t], ax[p][t]);
                        ay[p][t] = fmaf(ayk, wv[t], ay[p][t]);
                    }
                }
            }
        }

        __syncwarp();   // everyone done reading previous layer

#pragma unroll
        for (int p = 0; p < PPW; p++) {
#pragma unroll
            for (int t = 0; t < 8; t++) {
                float hh = tanhf(h[p][t]);
                float g  = 1.f - hh * hh;
                h[p][t]  = hh;
                ax[p][t] = g * ax[p][t];
                ay[p][t] = g * ay[p][t];
            }
            *(float4*)(&sh[warp][0][p][j0])     = make_float4(h[p][0], h[p][1], h[p][2], h[p][3]);
            *(float4*)(&sh[warp][0][p][j0 + 4]) = make_float4(h[p][4], h[p][5], h[p][6], h[p][7]);
            *(float4*)(&sh[warp][1][p][j0])     = make_float4(ax[p][0], ax[p][1], ax[p][2], ax[p][3]);
            *(float4*)(&sh[warp][1][p][j0 + 4]) = make_float4(ax[p][4], ax[p][5], ax[p][6], ax[p][7]);
            *(float4*)(&sh[warp][2][p][j0])     = make_float4(ay[p][0], ay[p][1], ay[p][2], ay[p][3]);
            *(float4*)(&sh[warp][2][p][j0 + 4]) = make_float4(ay[p][4], ay[p][5], ay[p][6], ay[p][7]);
        }
        __syncwarp();
    }

    // ---------------- output layer ----------------
    float pu[PPW], pv[PPW], pux[PPW], pvx[PPW], puy[PPW], pvy[PPW];
#pragma unroll
    for (int p = 0; p < PPW; p++) { pu[p]=pv[p]=pux[p]=pvx[p]=puy[p]=pvy[p]=0.f; }

#pragma unroll
    for (int t = 0; t < 8; t++) {
        int k = j0 + t;
        float wo0 = Wo[2 * k];
        float wo1 = Wo[2 * k + 1];
#pragma unroll
        for (int p = 0; p < PPW; p++) {
            pu[p]  = fmaf(h[p][t],  wo0, pu[p]);
            pv[p]  = fmaf(h[p][t],  wo1, pv[p]);
            pux[p] = fmaf(ax[p][t], wo0, pux[p]);
            pvx[p] = fmaf(ax[p][t], wo1, pvx[p]);
            puy[p] = fmaf(ay[p][t], wo0, puy[p]);
            pvy[p] = fmaf(ay[p][t], wo1, pvy[p]);
        }
    }
#pragma unroll
    for (int off = 16; off > 0; off >>= 1) {
#pragma unroll
        for (int p = 0; p < PPW; p++) {
            pu[p]  += __shfl_xor_sync(0xFFFFFFFFu, pu[p],  off);
            pv[p]  += __shfl_xor_sync(0xFFFFFFFFu, pv[p],  off);
            pux[p] += __shfl_xor_sync(0xFFFFFFFFu, pux[p], off);
            pvx[p] += __shfl_xor_sync(0xFFFFFFFFu, pvx[p], off);
            puy[p] += __shfl_xor_sync(0xFFFFFFFFu, puy[p], off);
            pvy[p] += __shfl_xor_sync(0xFFFFFFFFu, pvy[p], off);
        }
    }

    if (lane == 0) {
        float bo0 = bo[0], bo1 = bo[1];
#pragma unroll
        for (int p = 0; p < PPW; p++) {
            int pt = pbase + p;
            float u   = pu[p] + bo0;
            float v   = pv[p] + bo1;
            float u_x = pux[p], v_x = pvx[p];
            float u_y = puy[p], v_y = pvy[p];
            float u_xy = u_y + v_x;
            float sx  = C11f * u_x + C12f * v_y;
            float sy  = C12f * u_x + C11f * v_y;
            float sxy = C33f * u_xy;
            float sed = 0.5f * (sx * u_x + sy * v_y + sxy * u_xy);
            out[pt]               = u;
            out[npoints + pt]     = v;
            out[2 * npoints + pt] = sx;
            out[3 * npoints + pt] = sy;
            out[4 * npoints + pt] = sxy;
            out[5 * npoints + pt] = sed;
        }
    }
}

extern "C" void kernel_launch(void* const* d_in, const int* in_sizes, int n_in,
                              void* d_out, int out_size)
{
    const float* X  = (const float*)d_in[0];
    const float* W1 = (const float*)d_in[1];
    const float* b1 = (const float*)d_in[2];
    const float* W2 = (const float*)d_in[3];
    const float* b2 = (const float*)d_in[4];
    const float* W3 = (const float*)d_in[5];
    const float* b3 = (const float*)d_in[6];
    const float* Wo = (const float*)d_in[7];
    const float* bo = (const float*)d_in[8];
    float* out = (float*)d_out;

    const int npoints = in_sizes[0] / 2;                  // 262144
    const int ppb     = WPB * PPW;                        // 16 points per block
    const int nblocks = (npoints + ppb - 1) / ppb;        // 16384

    pinn_kernel<<<nblocks, WPB * 32>>>(X, W1, b1, W2, b2, W3, b3, Wo, bo,
                                       out, npoints);
}

// round 3
// speedup vs baseline: 2.2040x; 1.4175x over previous
#include <cuda_runtime.h>

#define HIDDEN 256
#define WPB    4          // warps per block
#define PPW    4          // points per warp (2 packed pairs)
#define NPAIR  2

#define C11f 1.0989010989010990f
#define C12f 0.3296703296703297f
#define C33f 0.3846153846153846f

typedef unsigned long long ull;

__device__ __forceinline__ ull pack2(float lo, float hi) {
    ull r; asm("mov.b64 %0, {%1,%2};" : "=l"(r) : "f"(lo), "f"(hi)); return r;
}
__device__ __forceinline__ void unpack2(ull v, float& lo, float& hi) {
    asm("mov.b64 {%0,%1}, %2;" : "=f"(lo), "=f"(hi) : "l"(v));
}
__device__ __forceinline__ void fma2(ull& d, ull a, ull b) {
    asm("fma.rn.f32x2 %0, %1, %2, %0;" : "+l"(d) : "l"(a), "l"(b));
}

// sh[warp][vec][pair][k] : packed (p_even, p_odd) activation value for neuron k
__global__ __launch_bounds__(WPB * 32, 2)
void pinn_kernel(
    const float* __restrict__ X,
    const float* __restrict__ W1, const float* __restrict__ b1,
    const float* __restrict__ W2, const float* __restrict__ b2,
    const float* __restrict__ W3, const float* __restrict__ b3,
    const float* __restrict__ Wo, const float* __restrict__ bo,
    float* __restrict__ out, int npoints)
{
    __shared__ ull sh[WPB][3][NPAIR][HIDDEN];   // 48 KB

    const int warp  = threadIdx.x >> 5;
    const int lane  = threadIdx.x & 31;
    const int pbase = (blockIdx.x * WPB + warp) * PPW;

    // lane owns neurons {4*lane+t, t<4} and {128+4*lane+(t-4), t>=4}
    const int nA = 4 * lane;          // first group base
    const int nB = 128 + 4 * lane;    // second group base

    // packed accumulators / activations: [pair][neuron-slot]
    ull h2[NPAIR][8], ax2[NPAIR][8], ay2[NPAIR][8];

    // ---------------- layer 1 ----------------
    {
        float xs[PPW], ys[PPW];
#pragma unroll
        for (int p = 0; p < PPW; p++) {
            xs[p] = X[2 * (pbase + p)];
            ys[p] = X[2 * (pbase + p) + 1];
        }
        float4 wxA = *(const float4*)(W1 + nA);
        float4 wxB = *(const float4*)(W1 + nB);
        float4 wyA = *(const float4*)(W1 + HIDDEN + nA);
        float4 wyB = *(const float4*)(W1 + HIDDEN + nB);
        float4 bA  = *(const float4*)(b1 + nA);
        float4 bB  = *(const float4*)(b1 + nB);
        float wx[8] = {wxA.x,wxA.y,wxA.z,wxA.w, wxB.x,wxB.y,wxB.z,wxB.w};
        float wy[8] = {wyA.x,wyA.y,wyA.z,wyA.w, wyB.x,wyB.y,wyB.z,wyB.w};
        float bb[8] = {bA.x,bA.y,bA.z,bA.w, bB.x,bB.y,bB.z,bB.w};

        float h[PPW][8], ax[PPW][8], ay[PPW][8];
#pragma unroll
        for (int t = 0; t < 8; t++) {
#pragma unroll
            for (int p = 0; p < PPW; p++) {
                float zz = fmaf(xs[p], wx[t], fmaf(ys[p], wy[t], bb[t]));
                float hh = tanhf(zz);
                float g  = 1.f - hh * hh;
                h[p][t]  = hh;
                ax[p][t] = g * wx[t];
                ay[p][t] = g * wy[t];
            }
        }
#pragma unroll
        for (int pr = 0; pr < NPAIR; pr++) {
#pragma unroll
            for (int t = 0; t < 8; t++) {
                h2[pr][t]  = pack2(h[2*pr][t],  h[2*pr+1][t]);
                ax2[pr][t] = pack2(ax[2*pr][t], ax[2*pr+1][t]);
                ay2[pr][t] = pack2(ay[2*pr][t], ay[2*pr+1][t]);
            }
        }
    }

    // store packed activations to SMEM
#pragma unroll
    for (int pr = 0; pr < NPAIR; pr++) {
        *(ulonglong2*)(&sh[warp][0][pr][nA])     = make_ulonglong2(h2[pr][0], h2[pr][1]);
        *(ulonglong2*)(&sh[warp][0][pr][nA + 2]) = make_ulonglong2(h2[pr][2], h2[pr][3]);
        *(ulonglong2*)(&sh[warp][0][pr][nB])     = make_ulonglong2(h2[pr][4], h2[pr][5]);
        *(ulonglong2*)(&sh[warp][0][pr][nB + 2]) = make_ulonglong2(h2[pr][6], h2[pr][7]);
        *(ulonglong2*)(&sh[warp][1][pr][nA])     = make_ulonglong2(ax2[pr][0], ax2[pr][1]);
        *(ulonglong2*)(&sh[warp][1][pr][nA + 2]) = make_ulonglong2(ax2[pr][2], ax2[pr][3]);
        *(ulonglong2*)(&sh[warp][1][pr][nB])     = make_ulonglong2(ax2[pr][4], ax2[pr][5]);
        *(ulonglong2*)(&sh[warp][1][pr][nB + 2]) = make_ulonglong2(ax2[pr][6], ax2[pr][7]);
        *(ulonglong2*)(&sh[warp][2][pr][nA])     = make_ulonglong2(ay2[pr][0], ay2[pr][1]);
        *(ulonglong2*)(&sh[warp][2][pr][nA + 2]) = make_ulonglong2(ay2[pr][2], ay2[pr][3]);
        *(ulonglong2*)(&sh[warp][2][pr][nB])     = make_ulonglong2(ay2[pr][4], ay2[pr][5]);
        *(ulonglong2*)(&sh[warp][2][pr][nB + 2]) = make_ulonglong2(ay2[pr][6], ay2[pr][7]);
    }
    __syncwarp();

    // ---------------- layers 2 & 3 ----------------
#pragma unroll 1
    for (int layer = 0; layer < 2; layer++) {
        const float* W = (layer == 0) ? W2 : W3;
        const float* b = (layer == 0) ? b2 : b3;

        float4 bA4 = *(const float4*)(b + nA);
        float4 bB4 = *(const float4*)(b + nB);
        float bb[8] = {bA4.x,bA4.y,bA4.z,bA4.w, bB4.x,bB4.y,bB4.z,bB4.w};

        ull z2[NPAIR][8], zx2[NPAIR][8], zy2[NPAIR][8];
#pragma unroll
        for (int pr = 0; pr < NPAIR; pr++)
#pragma unroll
            for (int t = 0; t < 8; t++) {
                z2[pr][t]  = pack2(bb[t], bb[t]);
                zx2[pr][t] = 0ull;
                zy2[pr][t] = 0ull;
            }

#pragma unroll 1
        for (int k4 = 0; k4 < HIDDEN; k4 += 4) {
            // packed activations for k..k+3, each pair: broadcast LDS.128
            ulonglong2 hA[NPAIR], hB[NPAIR], axA[NPAIR], axB[NPAIR], ayA[NPAIR], ayB[NPAIR];
#pragma unroll
            for (int pr = 0; pr < NPAIR; pr++) {
                hA[pr]  = *(const ulonglong2*)(&sh[warp][0][pr][k4]);
                hB[pr]  = *(const ulonglong2*)(&sh[warp][0][pr][k4 + 2]);
                axA[pr] = *(const ulonglong2*)(&sh[warp][1][pr][k4]);
                axB[pr] = *(const ulonglong2*)(&sh[warp][1][pr][k4 + 2]);
                ayA[pr] = *(const ulonglong2*)(&sh[warp][2][pr][k4]);
                ayB[pr] = *(const ulonglong2*)(&sh[warp][2][pr][k4 + 2]);
            }
#pragma unroll
            for (int kk = 0; kk < 4; kk++) {
                const float* wrow = W + (size_t)(k4 + kk) * HIDDEN;
                float4 w0 = *(const float4*)(wrow + nA);   // dense: 512B/warp
                float4 w1 = *(const float4*)(wrow + nB);
                float wv[8] = {w0.x,w0.y,w0.z,w0.w, w1.x,w1.y,w1.z,w1.w};
                ull ww[8];
#pragma unroll
                for (int t = 0; t < 8; t++) ww[t] = pack2(wv[t], wv[t]);
#pragma unroll
                for (int pr = 0; pr < NPAIR; pr++) {
                    ull hk  = (kk == 0) ? hA[pr].x  : (kk == 1) ? hA[pr].y  : (kk == 2) ? hB[pr].x  : hB[pr].y;
                    ull axk = (kk == 0) ? axA[pr].x : (kk == 1) ? axA[pr].y : (kk == 2) ? axB[pr].x : axB[pr].y;
                    ull ayk = (kk == 0) ? ayA[pr].x : (kk == 1) ? ayA[pr].y : (kk == 2) ? ayB[pr].x : ayB[pr].y;
#pragma unroll
                    for (int t = 0; t < 8; t++) {
                        fma2(z2[pr][t],  hk,  ww[t]);
                        fma2(zx2[pr][t], axk, ww[t]);
                        fma2(zy2[pr][t], ayk, ww[t]);
                    }
                }
            }
        }

        __syncwarp();   // all lanes done reading previous layer's SMEM

        // activation: unpack, tanh, repack
#pragma unroll
        for (int pr = 0; pr < NPAIR; pr++) {
#pragma unroll
            for (int t = 0; t < 8; t++) {
                float za, zb, xa, xb, ya, yb;
                unpack2(z2[pr][t],  za, zb);
                unpack2(zx2[pr][t], xa, xb);
                unpack2(zy2[pr][t], ya, yb);
                float ha = tanhf(za), hb = tanhf(zb);
                float ga = 1.f - ha * ha, gb = 1.f - hb * hb;
                h2[pr][t]  = pack2(ha, hb);
                ax2[pr][t] = pack2(ga * xa, gb * xb);
                ay2[pr][t] = pack2(ga * ya, gb * yb);
            }
            *(ulonglong2*)(&sh[warp][0][pr][nA])     = make_ulonglong2(h2[pr][0], h2[pr][1]);
            *(ulonglong2*)(&sh[warp][0][pr][nA + 2]) = make_ulonglong2(h2[pr][2], h2[pr][3]);
            *(ulonglong2*)(&sh[warp][0][pr][nB])     = make_ulonglong2(h2[pr][4], h2[pr][5]);
            *(ulonglong2*)(&sh[warp][0][pr][nB + 2]) = make_ulonglong2(h2[pr][6], h2[pr][7]);
            *(ulonglong2*)(&sh[warp][1][pr][nA])     = make_ulonglong2(ax2[pr][0], ax2[pr][1]);
            *(ulonglong2*)(&sh[warp][1][pr][nA + 2]) = make_ulonglong2(ax2[pr][2], ax2[pr][3]);
            *(ulonglong2*)(&sh[warp][1][pr][nB])     = make_ulonglong2(ax2[pr][4], ax2[pr][5]);
            *(ulonglong2*)(&sh[warp][1][pr][nB + 2]) = make_ulonglong2(ax2[pr][6], ax2[pr][7]);
            *(ulonglong2*)(&sh[warp][2][pr][nA])     = make_ulonglong2(ay2[pr][0], ay2[pr][1]);
            *(ulonglong2*)(&sh[warp][2][pr][nA + 2]) = make_ulonglong2(ay2[pr][2], ay2[pr][3]);
            *(ulonglong2*)(&sh[warp][2][pr][nB])     = make_ulonglong2(ay2[pr][4], ay2[pr][5]);
            *(ulonglong2*)(&sh[warp][2][pr][nB + 2]) = make_ulonglong2(ay2[pr][6], ay2[pr][7]);
        }
        __syncwarp();
    }

    // ---------------- output layer (packed) ----------------
    ull pu2[NPAIR], pv2[NPAIR], pux2[NPAIR], pvx2[NPAIR], puy2[NPAIR], pvy2[NPAIR];
#pragma unroll
    for (int pr = 0; pr < NPAIR; pr++) {
        pu2[pr] = pv2[pr] = pux2[pr] = pvx2[pr] = puy2[pr] = pvy2[pr] = 0ull;
    }
    // Wo rows for owned neurons: [nA..nA+3] and [nB..nB+3], 2 floats per row
    float4 woA0 = *(const float4*)(Wo + 2 * nA);       // rows nA, nA+1
    float4 woA1 = *(const float4*)(Wo + 2 * nA + 4);   // rows nA+2, nA+3
    float4 woB0 = *(const float4*)(Wo + 2 * nB);
    float4 woB1 = *(const float4*)(Wo + 2 * nB + 4);
    float wo0[8] = {woA0.x, woA0.z, woA1.x, woA1.z, woB0.x, woB0.z, woB1.x, woB1.z};
    float wo1[8] = {woA0.y, woA0.w, woA1.y, woA1.w, woB0.y, woB0.w, woB1.y, woB1.w};

#pragma unroll
    for (int t = 0; t < 8; t++) {
        ull w0p = pack2(wo0[t], wo0[t]);
        ull w1p = pack2(wo1[t], wo1[t]);
#pragma unroll
        for (int pr = 0; pr < NPAIR; pr++) {
            fma2(pu2[pr],  h2[pr][t],  w0p);
            fma2(pv2[pr],  h2[pr][t],  w1p);
            fma2(pux2[pr], ax2[pr][t], w0p);
            fma2(pvx2[pr], ax2[pr][t], w1p);
            fma2(puy2[pr], ay2[pr][t], w0p);
            fma2(pvy2[pr], ay2[pr][t], w1p);
        }
    }

    // butterfly reduce packed sums (lane-wise fp32 adds on both halves)
#pragma unroll
    for (int off = 16; off > 0; off >>= 1) {
#pragma unroll
        for (int pr = 0; pr < NPAIR; pr++) {
            ull o;
            o = __shfl_xor_sync(0xFFFFFFFFu, pu2[pr],  off);
            { float a,bq,c,d; unpack2(pu2[pr],a,bq); unpack2(o,c,d); pu2[pr]=pack2(a+c,bq+d); }
            o = __shfl_xor_sync(0xFFFFFFFFu, pv2[pr],  off);
            { float a,bq,c,d; unpack2(pv2[pr],a,bq); unpack2(o,c,d); pv2[pr]=pack2(a+c,bq+d); }
            o = __shfl_xor_sync(0xFFFFFFFFu, pux2[pr], off);
            { float a,bq,c,d; unpack2(pux2[pr],a,bq); unpack2(o,c,d); pux2[pr]=pack2(a+c,bq+d); }
            o = __shfl_xor_sync(0xFFFFFFFFu, pvx2[pr], off);
            { float a,bq,c,d; unpack2(pvx2[pr],a,bq); unpack2(o,c,d); pvx2[pr]=pack2(a+c,bq+d); }
            o = __shfl_xor_sync(0xFFFFFFFFu, puy2[pr], off);
            { float a,bq,c,d; unpack2(puy2[pr],a,bq); unpack2(o,c,d); puy2[pr]=pack2(a+c,bq+d); }
            o = __shfl_xor_sync(0xFFFFFFFFu, pvy2[pr], off);
            { float a,bq,c,d; unpack2(pvy2[pr],a,bq); unpack2(o,c,d); pvy2[pr]=pack2(a+c,bq+d); }
        }
    }

    if (lane == 0) {
        float bo0 = bo[0], bo1 = bo[1];
#pragma unroll
        for (int pr = 0; pr < NPAIR; pr++) {
            float puA, puB, pvA, pvB, puxA, puxB, pvxA, pvxB, puyA, puyB, pvyA, pvyB;
            unpack2(pu2[pr],  puA,  puB);
            unpack2(pv2[pr],  pvA,  pvB);
            unpack2(pux2[pr], puxA, puxB);
            unpack2(pvx2[pr], pvxA, pvxB);
            unpack2(puy2[pr], puyA, puyB);
            unpack2(pvy2[pr], pvyA, pvyB);
#pragma unroll
            for (int s = 0; s < 2; s++) {
                int pt = pbase + 2 * pr + s;
                float u   = (s ? puB  : puA)  + bo0;
                float v   = (s ? pvB  : pvA)  + bo1;
                float u_x = (s ? puxB : puxA);
                float v_x = (s ? pvxB : pvxA);
                float u_y = (s ? puyB : puyA);
                float v_y = (s ? pvyB : pvyA);
                float u_xy = u_y + v_x;
                float sx  = C11f * u_x + C12f * v_y;
                float sy  = C12f * u_x + C11f * v_y;
                float sxy = C33f * u_xy;
                float sed = 0.5f * (sx * u_x + sy * v_y + sxy * u_xy);
                out[pt]               = u;
                out[npoints + pt]     = v;
                out[2 * npoints + pt] = sx;
                out[3 * npoints + pt] = sy;
                out[4 * npoints + pt] = sxy;
                out[5 * npoints + pt] = sed;
            }
        }
    }
}

extern "C" void kernel_launch(void* const* d_in, const int* in_sizes, int n_in,
                              void* d_out, int out_size)
{
    const float* X  = (const float*)d_in[0];
    const float* W1 = (const float*)d_in[1];
    const float* b1 = (const float*)d_in[2];
    const float* W2 = (const float*)d_in[3];
    const float* b2 = (const float*)d_in[4];
    const float* W3 = (const float*)d_in[5];
    const float* b3 = (const float*)d_in[6];
    const float* Wo = (const float*)d_in[7];
    const float* bo = (const float*)d_in[8];
    float* out = (float*)d_out;

    const int npoints = in_sizes[0] / 2;              // 262144
    const int ppb     = WPB * PPW;                    // 16 points/block
    const int nblocks = (npoints + ppb - 1) / ppb;    // 16384

    pinn_kernel<<<nblocks, WPB * 32>>>(X, W1, b1, W2, b2, W3, b3, Wo, bo,
                                       out, npoints);
}